// round 14
// baseline (speedup 1.0000x reference)
#include <cuda_runtime.h>
#include <cuda_bf16.h>

// Problem constants
#define B_SZ   4
#define N_SZ   384
#define D_SZ   256
#define M_SZ   384
#define ROWS_PER_SEG (B_SZ * N_SZ)      // 1536
#define SEGS   3
#define NEG_BIG (-1.0e9f)

// Scratch for projected Q, K, V (device globals: no allocation allowed)
__device__ float g_Q[ROWS_PER_SEG * D_SZ];
__device__ float g_K[ROWS_PER_SEG * D_SZ];
__device__ float g_V[ROWS_PER_SEG * D_SZ];

// ---------------------------------------------------------------------------
// Kernel 1: fused projections  C_seg = A_seg @ W_seg + b_seg
//   seg 0: Q = q@Wq+bq, seg 1: K = k@Wk+bk, seg 2: V = v@Wv+bv
//   A: [1536, 256] row-major per segment, W: [256, 256], C: [1536, 256]
//   Tile: 64x64, TK=16, 256 threads, 4x4 micro-tile per thread.
// ---------------------------------------------------------------------------
#define TM 64
#define TN 64
#define TK 16

__global__ __launch_bounds__(256) void proj_kernel(
    const float* __restrict__ qin, const float* __restrict__ kin,
    const float* __restrict__ vin,
    const float* __restrict__ Wq, const float* __restrict__ bq,
    const float* __restrict__ Wk, const float* __restrict__ bk,
    const float* __restrict__ Wv, const float* __restrict__ bv)
{
    __shared__ float As[TK][TM];   // As[k][row]
    __shared__ float Ws[TK][TN];   // Ws[k][col]

    const int bx  = blockIdx.x;          // 0..71 (24 row tiles per segment * 3)
    const int by  = blockIdx.y;          // 0..3  col tiles
    const int seg = bx / (ROWS_PER_SEG / TM);
    const int r0  = (bx % (ROWS_PER_SEG / TM)) * TM;
    const int c0  = by * TN;

    const float* A    = (seg == 0) ? qin : (seg == 1) ? kin : vin;
    const float* W    = (seg == 0) ? Wq  : (seg == 1) ? Wk  : Wv;
    const float* bias = (seg == 0) ? bq  : (seg == 1) ? bk  : bv;
    float*       C    = (seg == 0) ? g_Q : (seg == 1) ? g_K : g_V;

    const int t  = threadIdx.x;
    const int tx = t & 15;         // 0..15 col group
    const int ty = t >> 4;         // 0..15 row group

    // Load index mapping
    const int a_row = t >> 2;          // 0..63
    const int a_k4  = (t & 3) * 4;     // 0,4,8,12
    const int w_row = t >> 4;          // 0..15
    const int w_c4  = (t & 15) * 4;    // 0..60

    float acc[4][4] = {};

    for (int kt = 0; kt < D_SZ; kt += TK) {
        float4 av = *(const float4*)&A[(r0 + a_row) * D_SZ + kt + a_k4];
        float4 wv = *(const float4*)&W[(kt + w_row) * D_SZ + c0 + w_c4];
        As[a_k4 + 0][a_row] = av.x;
        As[a_k4 + 1][a_row] = av.y;
        As[a_k4 + 2][a_row] = av.z;
        As[a_k4 + 3][a_row] = av.w;
        *(float4*)&Ws[w_row][w_c4] = wv;
        __syncthreads();

        #pragma unroll
        for (int kk = 0; kk < TK; kk++) {
            float4 a4 = *(const float4*)&As[kk][ty * 4];
            float4 w4 = *(const float4*)&Ws[kk][tx * 4];
            float a[4] = {a4.x, a4.y, a4.z, a4.w};
            float w[4] = {w4.x, w4.y, w4.z, w4.w};
            #pragma unroll
            for (int i = 0; i < 4; i++)
                #pragma unroll
                for (int j = 0; j < 4; j++)
                    acc[i][j] = fmaf(a[i], w[j], acc[i][j]);
        }
        __syncthreads();
    }

    // Epilogue: add bias, store
    float4 bv4 = *(const float4*)&bias[c0 + tx * 4];
    #pragma unroll
    for (int i = 0; i < 4; i++) {
        const int r = r0 + ty * 4 + i;
        float4 o;
        o.x = acc[i][0] + bv4.x;
        o.y = acc[i][1] + bv4.y;
        o.z = acc[i][2] + bv4.z;
        o.w = acc[i][3] + bv4.w;
        *(float4*)&C[r * D_SZ + c0 + tx * 4] = o;
    }
}

// ---------------------------------------------------------------------------
// Kernel 2: main loop
//   out[b,n,d] = sum_m tanh(Q[b,n,d]*K[b,m,d] + bias[n,m]) * V[b,m,d]
//   Block = (b, 8-n tile, 128-d half) -> grid (48, 4, 2) = 384 blocks, 128 thr.
//   Thread owns one d; q[8]/acc[8] in registers; K/V loaded once per m
//   (coalesced 128B warp loads) and reused across 8 n. Mask bias tile in smem.
//   tanh via HW MUFU.TANH (tanh.approx.f32): MUFU-bound.
// ---------------------------------------------------------------------------
#define TNR 8   // n per block

__device__ __forceinline__ float tanh_fast(float x) {
    float r;
    asm("tanh.approx.f32 %0, %1;" : "=f"(r) : "f"(x));
    return r;
}

__global__ __launch_bounds__(128) void opmhsa_main(
    const int* __restrict__ mask, float* __restrict__ out)
{
    const int nt = blockIdx.x;    // 0..47
    const int b  = blockIdx.y;    // 0..3
    const int dh = blockIdx.z;    // 0..1
    const int tid = threadIdx.x;  // 0..127
    const int d  = dh * 128 + tid;
    const int n0 = nt * TNR;

    __shared__ float bias_s[TNR][M_SZ];  // 12 KB

    // Load mask tile -> float bias (mask ? -1e9 : 0). [B,1,N,M] layout.
    const int* mrow = mask + (b * N_SZ + n0) * M_SZ;
    for (int i = tid; i < TNR * M_SZ; i += 128)
        bias_s[i / M_SZ][i % M_SZ] = mrow[i] ? NEG_BIG : 0.0f;
    __syncthreads();

    const float* Qb = g_Q + (b * N_SZ + n0) * D_SZ + d;
    const float* Kb = g_K + b * N_SZ * D_SZ + d;
    const float* Vb = g_V + b * N_SZ * D_SZ + d;

    float qv[TNR], acc[TNR];
    #pragma unroll
    for (int i = 0; i < TNR; i++) {
        qv[i]  = Qb[i * D_SZ];
        acc[i] = 0.0f;
    }

    #pragma unroll 4
    for (int m = 0; m < M_SZ; m++) {
        const float kk = Kb[m * D_SZ];
        const float vv = Vb[m * D_SZ];
        #pragma unroll
        for (int i = 0; i < TNR; i++) {
            float s = fmaf(qv[i], kk, bias_s[i][m]);
            float t = tanh_fast(s);
            acc[i] = fmaf(t, vv, acc[i]);
        }
    }

    float* ob = out + (b * N_SZ + n0) * D_SZ + d;
    #pragma unroll
    for (int i = 0; i < TNR; i++)
        ob[i * D_SZ] = acc[i];
}

// ---------------------------------------------------------------------------
// Launch
// ---------------------------------------------------------------------------
extern "C" void kernel_launch(void* const* d_in, const int* in_sizes, int n_in,
                              void* d_out, int out_size)
{
    const float* q    = (const float*)d_in[0];
    const float* k    = (const float*)d_in[1];
    const float* v    = (const float*)d_in[2];
    const int*   mask = (const int*)  d_in[3];
    const float* Wq   = (const float*)d_in[4];
    const float* bq   = (const float*)d_in[5];
    const float* Wk   = (const float*)d_in[6];
    const float* bk   = (const float*)d_in[7];
    const float* Wv   = (const float*)d_in[8];
    const float* bv   = (const float*)d_in[9];
    float* out = (float*)d_out;

    // Projections: 3 segments * 24 row tiles = 72, 4 col tiles
    proj_kernel<<<dim3(72, 4), 256>>>(q, k, v, Wq, bq, Wk, bk, Wv, bv);

    // Main loop: 48 n-tiles * 4 batches * 2 d-halves = 384 blocks
    opmhsa_main<<<dim3(48, 4, 2), 128>>>(mask, out);
}

// round 15
// speedup vs baseline: 1.0254x; 1.0254x over previous
#include <cuda_runtime.h>
#include <cuda_bf16.h>

// Problem constants
#define B_SZ   4
#define N_SZ   384
#define D_SZ   256
#define M_SZ   384
#define ROWS_PER_SEG (B_SZ * N_SZ)      // 1536
#define SEGS   3
#define NEG_BIG (-1.0e9f)

// Scratch for projected Q, K, V (device globals: no allocation allowed)
__device__ float g_Q[ROWS_PER_SEG * D_SZ];
__device__ float g_K[ROWS_PER_SEG * D_SZ];
__device__ float g_V[ROWS_PER_SEG * D_SZ];

// ---------------------------------------------------------------------------
// Kernel 1: fused projections  C_seg = A_seg @ W_seg + b_seg
//   seg 0: Q = q@Wq+bq, seg 1: K = k@Wk+bk, seg 2: V = v@Wv+bv
//   A: [1536, 256] row-major per segment, W: [256, 256], C: [1536, 256]
//   Tile: 64x64, TK=16, 256 threads, 4x4 micro-tile per thread.
// ---------------------------------------------------------------------------
#define TM 64
#define TN 64
#define TK 16

__global__ __launch_bounds__(256) void proj_kernel(
    const float* __restrict__ qin, const float* __restrict__ kin,
    const float* __restrict__ vin,
    const float* __restrict__ Wq, const float* __restrict__ bq,
    const float* __restrict__ Wk, const float* __restrict__ bk,
    const float* __restrict__ Wv, const float* __restrict__ bv)
{
    __shared__ float As[TK][TM];   // As[k][row]
    __shared__ float Ws[TK][TN];   // Ws[k][col]

    const int bx  = blockIdx.x;          // 0..71 (24 row tiles per segment * 3)
    const int by  = blockIdx.y;          // 0..3  col tiles
    const int seg = bx / (ROWS_PER_SEG / TM);
    const int r0  = (bx % (ROWS_PER_SEG / TM)) * TM;
    const int c0  = by * TN;

    const float* A    = (seg == 0) ? qin : (seg == 1) ? kin : vin;
    const float* W    = (seg == 0) ? Wq  : (seg == 1) ? Wk  : Wv;
    const float* bias = (seg == 0) ? bq  : (seg == 1) ? bk  : bv;
    float*       C    = (seg == 0) ? g_Q : (seg == 1) ? g_K : g_V;

    const int t  = threadIdx.x;
    const int tx = t & 15;         // 0..15 col group
    const int ty = t >> 4;         // 0..15 row group

    // Load index mapping
    const int a_row = t >> 2;          // 0..63
    const int a_k4  = (t & 3) * 4;     // 0,4,8,12
    const int w_row = t >> 4;          // 0..15
    const int w_c4  = (t & 15) * 4;    // 0..60

    float acc[4][4] = {};

    for (int kt = 0; kt < D_SZ; kt += TK) {
        float4 av = *(const float4*)&A[(r0 + a_row) * D_SZ + kt + a_k4];
        float4 wv = *(const float4*)&W[(kt + w_row) * D_SZ + c0 + w_c4];
        As[a_k4 + 0][a_row] = av.x;
        As[a_k4 + 1][a_row] = av.y;
        As[a_k4 + 2][a_row] = av.z;
        As[a_k4 + 3][a_row] = av.w;
        *(float4*)&Ws[w_row][w_c4] = wv;
        __syncthreads();

        #pragma unroll
        for (int kk = 0; kk < TK; kk++) {
            float4 a4 = *(const float4*)&As[kk][ty * 4];
            float4 w4 = *(const float4*)&Ws[kk][tx * 4];
            float a[4] = {a4.x, a4.y, a4.z, a4.w};
            float w[4] = {w4.x, w4.y, w4.z, w4.w};
            #pragma unroll
            for (int i = 0; i < 4; i++)
                #pragma unroll
                for (int j = 0; j < 4; j++)
                    acc[i][j] = fmaf(a[i], w[j], acc[i][j]);
        }
        __syncthreads();
    }

    // Epilogue: add bias, store
    float4 bv4 = *(const float4*)&bias[c0 + tx * 4];
    #pragma unroll
    for (int i = 0; i < 4; i++) {
        const int r = r0 + ty * 4 + i;
        float4 o;
        o.x = acc[i][0] + bv4.x;
        o.y = acc[i][1] + bv4.y;
        o.z = acc[i][2] + bv4.z;
        o.w = acc[i][3] + bv4.w;
        *(float4*)&C[r * D_SZ + c0 + tx * 4] = o;
    }
}

// ---------------------------------------------------------------------------
// Kernel 2: main loop
//   out[b,n,d] = sum_m tanh(Q[b,n,d]*K[b,m,d] + bias[n,m]) * V[b,m,d]
//   Block = (b, 8-n tile, 128-d half) -> grid (48, 4, 2) = 384 blocks, 128 thr.
//   Thread owns one d; q[8]/acc[8] in registers; K/V loaded once per m
//   (coalesced 128B warp loads) and reused across 8 n. Mask bias tile in smem.
//   tanh via HW MUFU.TANH (tanh.approx.f32): MUFU-bound.
// ---------------------------------------------------------------------------
#define TNR 8   // n per block

__device__ __forceinline__ float tanh_fast(float x) {
    float r;
    asm("tanh.approx.f32 %0, %1;" : "=f"(r) : "f"(x));
    return r;
}

__global__ __launch_bounds__(128) void opmhsa_main(
    const int* __restrict__ mask, float* __restrict__ out)
{
    const int nt = blockIdx.x;    // 0..47
    const int b  = blockIdx.y;    // 0..3
    const int dh = blockIdx.z;    // 0..1
    const int tid = threadIdx.x;  // 0..127
    const int d  = dh * 128 + tid;
    const int n0 = nt * TNR;

    __shared__ float bias_s[TNR][M_SZ];  // 12 KB

    // Load mask tile -> float bias (mask ? -1e9 : 0). [B,1,N,M] layout.
    const int* mrow = mask + (b * N_SZ + n0) * M_SZ;
    for (int i = tid; i < TNR * M_SZ; i += 128)
        bias_s[i / M_SZ][i % M_SZ] = mrow[i] ? NEG_BIG : 0.0f;
    __syncthreads();

    const float* Qb = g_Q + (b * N_SZ + n0) * D_SZ + d;
    const float* Kb = g_K + b * N_SZ * D_SZ + d;
    const float* Vb = g_V + b * N_SZ * D_SZ + d;

    float qv[TNR], acc[TNR];
    #pragma unroll
    for (int i = 0; i < TNR; i++) {
        qv[i]  = Qb[i * D_SZ];
        acc[i] = 0.0f;
    }

    #pragma unroll 4
    for (int m = 0; m < M_SZ; m++) {
        const float kk = Kb[m * D_SZ];
        const float vv = Vb[m * D_SZ];
        #pragma unroll
        for (int i = 0; i < TNR; i++) {
            float s = fmaf(qv[i], kk, bias_s[i][m]);
            float t = tanh_fast(s);
            acc[i] = fmaf(t, vv, acc[i]);
        }
    }

    float* ob = out + (b * N_SZ + n0) * D_SZ + d;
    #pragma unroll
    for (int i = 0; i < TNR; i++)
        ob[i * D_SZ] = acc[i];
}

// ---------------------------------------------------------------------------
// Launch
// ---------------------------------------------------------------------------
extern "C" void kernel_launch(void* const* d_in, const int* in_sizes, int n_in,
                              void* d_out, int out_size)
{
    const float* q    = (const float*)d_in[0];
    const float* k    = (const float*)d_in[1];
    const float* v    = (const float*)d_in[2];
    const int*   mask = (const int*)  d_in[3];
    const float* Wq   = (const float*)d_in[4];
    const float* bq   = (const float*)d_in[5];
    const float* Wk   = (const float*)d_in[6];
    const float* bk   = (const float*)d_in[7];
    const float* Wv   = (const float*)d_in[8];
    const float* bv   = (const float*)d_in[9];
    float* out = (float*)d_out;

    // Projections: 3 segments * 24 row tiles = 72, 4 col tiles
    proj_kernel<<<dim3(72, 4), 256>>>(q, k, v, Wq, bq, Wk, bk, Wv, bv);

    // Main loop: 48 n-tiles * 4 batches * 2 d-halves = 384 blocks
    opmhsa_main<<<dim3(48, 4, 2), 128>>>(mask, out);
}

// round 16
// speedup vs baseline: 1.0360x; 1.0104x over previous
#include <cuda_runtime.h>
#include <cuda_bf16.h>

// Problem constants
#define B_SZ   4
#define N_SZ   384
#define D_SZ   256
#define M_SZ   384
#define ROWS_PER_SEG (B_SZ * N_SZ)      // 1536
#define SEGS   3
#define NEG_BIG (-1.0e9f)

// Scratch for projected Q, K, V (device globals: no allocation allowed)
__device__ float g_Q[ROWS_PER_SEG * D_SZ];
__device__ float g_K[ROWS_PER_SEG * D_SZ];
__device__ float g_V[ROWS_PER_SEG * D_SZ];

// ---------------------------------------------------------------------------
// Kernel 1: fused projections  C_seg = A_seg @ W_seg + b_seg
//   seg 0: Q = q@Wq+bq, seg 1: K = k@Wk+bk, seg 2: V = v@Wv+bv
//   A: [1536, 256] row-major per segment, W: [256, 256], C: [1536, 256]
//   Tile: 64x64, TK=16, 256 threads, 4x4 micro-tile per thread.
// ---------------------------------------------------------------------------
#define TM 64
#define TN 64
#define TK 16

__global__ __launch_bounds__(256) void proj_kernel(
    const float* __restrict__ qin, const float* __restrict__ kin,
    const float* __restrict__ vin,
    const float* __restrict__ Wq, const float* __restrict__ bq,
    const float* __restrict__ Wk, const float* __restrict__ bk,
    const float* __restrict__ Wv, const float* __restrict__ bv)
{
    __shared__ float As[TK][TM];   // As[k][row]
    __shared__ float Ws[TK][TN];   // Ws[k][col]

    const int bx  = blockIdx.x;          // 0..71 (24 row tiles per segment * 3)
    const int by  = blockIdx.y;          // 0..3  col tiles
    const int seg = bx / (ROWS_PER_SEG / TM);
    const int r0  = (bx % (ROWS_PER_SEG / TM)) * TM;
    const int c0  = by * TN;

    const float* A    = (seg == 0) ? qin : (seg == 1) ? kin : vin;
    const float* W    = (seg == 0) ? Wq  : (seg == 1) ? Wk  : Wv;
    const float* bias = (seg == 0) ? bq  : (seg == 1) ? bk  : bv;
    float*       C    = (seg == 0) ? g_Q : (seg == 1) ? g_K : g_V;

    const int t  = threadIdx.x;
    const int tx = t & 15;         // 0..15 col group
    const int ty = t >> 4;         // 0..15 row group

    // Load index mapping
    const int a_row = t >> 2;          // 0..63
    const int a_k4  = (t & 3) * 4;     // 0,4,8,12
    const int w_row = t >> 4;          // 0..15
    const int w_c4  = (t & 15) * 4;    // 0..60

    float acc[4][4] = {};

    for (int kt = 0; kt < D_SZ; kt += TK) {
        float4 av = *(const float4*)&A[(r0 + a_row) * D_SZ + kt + a_k4];
        float4 wv = *(const float4*)&W[(kt + w_row) * D_SZ + c0 + w_c4];
        As[a_k4 + 0][a_row] = av.x;
        As[a_k4 + 1][a_row] = av.y;
        As[a_k4 + 2][a_row] = av.z;
        As[a_k4 + 3][a_row] = av.w;
        *(float4*)&Ws[w_row][w_c4] = wv;
        __syncthreads();

        #pragma unroll
        for (int kk = 0; kk < TK; kk++) {
            float4 a4 = *(const float4*)&As[kk][ty * 4];
            float4 w4 = *(const float4*)&Ws[kk][tx * 4];
            float a[4] = {a4.x, a4.y, a4.z, a4.w};
            float w[4] = {w4.x, w4.y, w4.z, w4.w};
            #pragma unroll
            for (int i = 0; i < 4; i++)
                #pragma unroll
                for (int j = 0; j < 4; j++)
                    acc[i][j] = fmaf(a[i], w[j], acc[i][j]);
        }
        __syncthreads();
    }

    // Epilogue: add bias, store
    float4 bv4 = *(const float4*)&bias[c0 + tx * 4];
    #pragma unroll
    for (int i = 0; i < 4; i++) {
        const int r = r0 + ty * 4 + i;
        float4 o;
        o.x = acc[i][0] + bv4.x;
        o.y = acc[i][1] + bv4.y;
        o.z = acc[i][2] + bv4.z;
        o.w = acc[i][3] + bv4.w;
        *(float4*)&C[r * D_SZ + c0 + tx * 4] = o;
    }
}

// ---------------------------------------------------------------------------
// Kernel 2: main loop
//   out[b,n,d] = sum_m tanh(Q[b,n,d]*K[b,m,d] + bias[n,m]) * V[b,m,d]
//   Block = (b, 8-n tile, 128-d half) -> grid (48, 4, 2) = 384 blocks, 128 thr.
//   Thread owns one d; q[8]/acc[8] in registers; K/V loaded once per m
//   (coalesced 128B warp loads) and reused across 8 n. Mask bias tile in smem.
//   tanh via HW MUFU.TANH (tanh.approx.f32): MUFU-bound.
// ---------------------------------------------------------------------------
#define TNR 8   // n per block

__device__ __forceinline__ float tanh_fast(float x) {
    float r;
    asm("tanh.approx.f32 %0, %1;" : "=f"(r) : "f"(x));
    return r;
}

__global__ __launch_bounds__(128) void opmhsa_main(
    const int* __restrict__ mask, float* __restrict__ out)
{
    const int nt = blockIdx.x;    // 0..47
    const int b  = blockIdx.y;    // 0..3
    const int dh = blockIdx.z;    // 0..1
    const int tid = threadIdx.x;  // 0..127
    const int d  = dh * 128 + tid;
    const int n0 = nt * TNR;

    __shared__ float bias_s[TNR][M_SZ];  // 12 KB

    // Load mask tile -> float bias (mask ? -1e9 : 0). [B,1,N,M] layout.
    const int* mrow = mask + (b * N_SZ + n0) * M_SZ;
    for (int i = tid; i < TNR * M_SZ; i += 128)
        bias_s[i / M_SZ][i % M_SZ] = mrow[i] ? NEG_BIG : 0.0f;
    __syncthreads();

    const float* Qb = g_Q + (b * N_SZ + n0) * D_SZ + d;
    const float* Kb = g_K + b * N_SZ * D_SZ + d;
    const float* Vb = g_V + b * N_SZ * D_SZ + d;

    float qv[TNR], acc[TNR];
    #pragma unroll
    for (int i = 0; i < TNR; i++) {
        qv[i]  = Qb[i * D_SZ];
        acc[i] = 0.0f;
    }

    #pragma unroll 4
    for (int m = 0; m < M_SZ; m++) {
        const float kk = Kb[m * D_SZ];
        const float vv = Vb[m * D_SZ];
        #pragma unroll
        for (int i = 0; i < TNR; i++) {
            float s = fmaf(qv[i], kk, bias_s[i][m]);
            float t = tanh_fast(s);
            acc[i] = fmaf(t, vv, acc[i]);
        }
    }

    float* ob = out + (b * N_SZ + n0) * D_SZ + d;
    #pragma unroll
    for (int i = 0; i < TNR; i++)
        ob[i * D_SZ] = acc[i];
}

// ---------------------------------------------------------------------------
// Launch
// ---------------------------------------------------------------------------
extern "C" void kernel_launch(void* const* d_in, const int* in_sizes, int n_in,
                              void* d_out, int out_size)
{
    const float* q    = (const float*)d_in[0];
    const float* k    = (const float*)d_in[1];
    const float* v    = (const float*)d_in[2];
    const int*   mask = (const int*)  d_in[3];
    const float* Wq   = (const float*)d_in[4];
    const float* bq   = (const float*)d_in[5];
    const float* Wk   = (const float*)d_in[6];
    const float* bk   = (const float*)d_in[7];
    const float* Wv   = (const float*)d_in[8];
    const float* bv   = (const float*)d_in[9];
    float* out = (float*)d_out;

    // Projections: 3 segments * 24 row tiles = 72, 4 col tiles
    proj_kernel<<<dim3(72, 4), 256>>>(q, k, v, Wq, bq, Wk, bk, Wv, bv);

    // Main loop: 48 n-tiles * 4 batches * 2 d-halves = 384 blocks
    opmhsa_main<<<dim3(48, 4, 2), 128>>>(mask, out);
}

// round 17
// speedup vs baseline: 1.3244x; 1.2783x over previous
#include <cuda_runtime.h>
#include <cuda_bf16.h>

// Problem constants
#define B_SZ   4
#define N_SZ   384
#define D_SZ   256
#define M_SZ   384
#define ROWS_PER_SEG (B_SZ * N_SZ)      // 1536
#define NEG_BIG (-1.0e9f)

// Scratch for projected Q, K, V (device globals: no allocation allowed)
__device__ float g_Q[ROWS_PER_SEG * D_SZ];
__device__ float g_K[ROWS_PER_SEG * D_SZ];
__device__ float g_V[ROWS_PER_SEG * D_SZ];

// ---------------------------------------------------------------------------
// Kernel 1: fused projections  C_seg = A_seg @ W_seg + b_seg   (unchanged)
// ---------------------------------------------------------------------------
#define TM 64
#define TN 64
#define TK 16

__global__ __launch_bounds__(256) void proj_kernel(
    const float* __restrict__ qin, const float* __restrict__ kin,
    const float* __restrict__ vin,
    const float* __restrict__ Wq, const float* __restrict__ bq,
    const float* __restrict__ Wk, const float* __restrict__ bk,
    const float* __restrict__ Wv, const float* __restrict__ bv)
{
    __shared__ float As[TK][TM];   // As[k][row]
    __shared__ float Ws[TK][TN];   // Ws[k][col]

    const int bx  = blockIdx.x;          // 0..71 (24 row tiles per segment * 3)
    const int by  = blockIdx.y;          // 0..3  col tiles
    const int seg = bx / (ROWS_PER_SEG / TM);
    const int r0  = (bx % (ROWS_PER_SEG / TM)) * TM;
    const int c0  = by * TN;

    const float* A    = (seg == 0) ? qin : (seg == 1) ? kin : vin;
    const float* W    = (seg == 0) ? Wq  : (seg == 1) ? Wk  : Wv;
    const float* bias = (seg == 0) ? bq  : (seg == 1) ? bk  : bv;
    float*       C    = (seg == 0) ? g_Q : (seg == 1) ? g_K : g_V;

    const int t  = threadIdx.x;
    const int tx = t & 15;         // 0..15 col group
    const int ty = t >> 4;         // 0..15 row group

    const int a_row = t >> 2;          // 0..63
    const int a_k4  = (t & 3) * 4;     // 0,4,8,12
    const int w_row = t >> 4;          // 0..15
    const int w_c4  = (t & 15) * 4;    // 0..60

    float acc[4][4] = {};

    for (int kt = 0; kt < D_SZ; kt += TK) {
        float4 av = *(const float4*)&A[(r0 + a_row) * D_SZ + kt + a_k4];
        float4 wv = *(const float4*)&W[(kt + w_row) * D_SZ + c0 + w_c4];
        As[a_k4 + 0][a_row] = av.x;
        As[a_k4 + 1][a_row] = av.y;
        As[a_k4 + 2][a_row] = av.z;
        As[a_k4 + 3][a_row] = av.w;
        *(float4*)&Ws[w_row][w_c4] = wv;
        __syncthreads();

        #pragma unroll
        for (int kk = 0; kk < TK; kk++) {
            float4 a4 = *(const float4*)&As[kk][ty * 4];
            float4 w4 = *(const float4*)&Ws[kk][tx * 4];
            float a[4] = {a4.x, a4.y, a4.z, a4.w};
            float w[4] = {w4.x, w4.y, w4.z, w4.w};
            #pragma unroll
            for (int i = 0; i < 4; i++)
                #pragma unroll
                for (int j = 0; j < 4; j++)
                    acc[i][j] = fmaf(a[i], w[j], acc[i][j]);
        }
        __syncthreads();
    }

    float4 bv4 = *(const float4*)&bias[c0 + tx * 4];
    #pragma unroll
    for (int i = 0; i < 4; i++) {
        const int r = r0 + ty * 4 + i;
        float4 o;
        o.x = acc[i][0] + bv4.x;
        o.y = acc[i][1] + bv4.y;
        o.z = acc[i][2] + bv4.z;
        o.w = acc[i][3] + bv4.w;
        *(float4*)&C[r * D_SZ + c0 + tx * 4] = o;
    }
}

// ---------------------------------------------------------------------------
// Kernel 2: main loop with warp-uniform mask compaction + float4 d-vectorization
//
//   out[b,n,d] = sum_{m unmasked} tanh(Q[b,n,d]*K[b,m,d]) * V[b,m,d]
//              + sum_{m masked}   (-V[b,m,d])          (tanh(-1e9+x) == -1 in fp32)
//
//   Block = (n, b). 64 threads; thread owns 4 consecutive d's (float4).
//   Warp 0 compacts the mask row into a single smem index list:
//     [0, cnt)      -> unmasked m's   (tanh loop, MUFU)
//     [cnt, 384)    -> masked m's     (FADD-only loop, no MUFU)
//   Grid = 1536 blocks -> ~20.8 warps/SM. MUFU work halved vs uniform loop.
// ---------------------------------------------------------------------------
__device__ __forceinline__ float tanh_fast(float x) {
    float r;
    asm("tanh.approx.f32 %0, %1;" : "=f"(r) : "f"(x));
    return r;
}

__global__ __launch_bounds__(64) void opmhsa_main(
    const int* __restrict__ mask, float* __restrict__ out)
{
    const int n   = blockIdx.x;   // 0..383
    const int b   = blockIdx.y;   // 0..3
    const int tid = threadIdx.x;  // 0..63  -> d = tid*4 .. tid*4+3

    __shared__ unsigned short list_s[M_SZ];
    __shared__ int cnt_s;

    // --- Warp 0: compact mask row (unmasked front, masked back) ---
    const int* mrow = mask + (b * N_SZ + n) * M_SZ;   // [B,1,N,M]
    if (tid < 32) {
        int front = 0;
        int back  = M_SZ;
        const unsigned lt = (1u << tid) - 1u;   // lanemask_lt
        #pragma unroll
        for (int c = 0; c < M_SZ / 32; c++) {
            const int m  = c * 32 + tid;
            const int mk = mrow[m];
            const unsigned bal = __ballot_sync(0xffffffffu, mk == 0);
            if (mk == 0)
                list_s[front + __popc(bal & lt)] = (unsigned short)m;
            else
                list_s[back - 1 - __popc(~bal & lt)] = (unsigned short)m;
            const int nun = __popc(bal);
            front += nun;
            back  -= 32 - nun;
        }
        if (tid == 0) cnt_s = front;
    }
    __syncthreads();

    const float4* K4 = (const float4*)g_K + b * N_SZ * (D_SZ / 4);
    const float4* V4 = (const float4*)g_V + b * N_SZ * (D_SZ / 4);
    const float4  q4 = ((const float4*)g_Q)[(b * N_SZ + n) * (D_SZ / 4) + tid];

    float4 acc = make_float4(0.f, 0.f, 0.f, 0.f);
    const int cnt = cnt_s;

    // --- Unmasked m's: full tanh path (bias == 0) ---
    #pragma unroll 4
    for (int j = 0; j < cnt; j++) {
        const int m = list_s[j];
        const float4 kk = K4[m * (D_SZ / 4) + tid];
        const float4 vv = V4[m * (D_SZ / 4) + tid];
        acc.x = fmaf(tanh_fast(q4.x * kk.x), vv.x, acc.x);
        acc.y = fmaf(tanh_fast(q4.y * kk.y), vv.y, acc.y);
        acc.z = fmaf(tanh_fast(q4.z * kk.z), vv.z, acc.z);
        acc.w = fmaf(tanh_fast(q4.w * kk.w), vv.w, acc.w);
    }

    // --- Masked m's: tanh == -1 exactly -> acc -= v ---
    #pragma unroll 4
    for (int j = cnt; j < M_SZ; j++) {
        const int m = list_s[j];
        const float4 vv = V4[m * (D_SZ / 4) + tid];
        acc.x -= vv.x;
        acc.y -= vv.y;
        acc.z -= vv.z;
        acc.w -= vv.w;
    }

    ((float4*)out)[(b * N_SZ + n) * (D_SZ / 4) + tid] = acc;
}

// ---------------------------------------------------------------------------
// Launch
// ---------------------------------------------------------------------------
extern "C" void kernel_launch(void* const* d_in, const int* in_sizes, int n_in,
                              void* d_out, int out_size)
{
    const float* q    = (const float*)d_in[0];
    const float* k    = (const float*)d_in[1];
    const float* v    = (const float*)d_in[2];
    const int*   mask = (const int*)  d_in[3];
    const float* Wq   = (const float*)d_in[4];
    const float* bq   = (const float*)d_in[5];
    const float* Wk   = (const float*)d_in[6];
    const float* bk   = (const float*)d_in[7];
    const float* Wv   = (const float*)d_in[8];
    const float* bv   = (const float*)d_in[9];
    float* out = (float*)d_out;

    // Projections: 3 segments * 24 row tiles = 72, 4 col tiles
    proj_kernel<<<dim3(72, 4), 256>>>(q, k, v, Wq, bq, Wk, bk, Wv, bv);

    // Main loop: one block per (n, b); 64 threads, 4 d's each
    opmhsa_main<<<dim3(N_SZ, B_SZ), 64>>>(mask, out);
}